// round 1
// baseline (speedup 1.0000x reference)
#include <cuda_runtime.h>
#include <stdint.h>

// Problem constants (fixed-shape bench): N=2e6 points, C=64 floats, bs=8,
// max_length derived from out_size on the host side.
#define NBINS      8
#define THREADS    256
#define PPB        2048                 // points per block
#define ITEMS      (PPB / THREADS)      // 8 contiguous points per thread
#define MAX_BLOCKS 8192

// Scratch (no allocations allowed) — recomputed deterministically every call.
__device__ int g_blockCounts[MAX_BLOCKS * NBINS];
__device__ int g_blockOffsets[MAX_BLOCKS * NBINS];
__device__ int g_totals[NBINS];

// ---------------------------------------------------------------------------
// Pass 1: per-block 8-bin histogram of inds[:,0]
// ---------------------------------------------------------------------------
__global__ __launch_bounds__(THREADS)
void count_kernel(const int* __restrict__ inds, int n) {
    __shared__ int s_cnt[NBINS];
    int tid = threadIdx.x;
    if (tid < NBINS) s_cnt[tid] = 0;
    __syncthreads();

    int base = blockIdx.x * PPB;
    int end  = min(base + PPB, n);
    for (int i = base + tid; i < end; i += THREADS) {
        int b = inds[(size_t)i * 4];
        atomicAdd(&s_cnt[b & (NBINS - 1)], 1);
    }
    __syncthreads();
    if (tid < NBINS) g_blockCounts[blockIdx.x * NBINS + tid] = s_cnt[tid];
}

// ---------------------------------------------------------------------------
// Pass 2: exclusive scan of block counts per bin (single block, 1024 threads,
// 128 threads per bin so the cross-block chain is parallel, not serial-977).
// ---------------------------------------------------------------------------
__global__ __launch_bounds__(1024)
void scan_kernel(int nblocks) {
    const int TPB_BIN = 128;
    int b = threadIdx.x / TPB_BIN;   // bin 0..7
    int t = threadIdx.x % TPB_BIN;
    int per = (nblocks + TPB_BIN - 1) / TPB_BIN;
    int lo = t * per;
    int hi = min(lo + per, nblocks);

    int sum = 0;
    for (int blk = lo; blk < hi; blk++)
        sum += g_blockCounts[blk * NBINS + b];

    __shared__ int s_part[NBINS][TPB_BIN];
    s_part[b][t] = sum;
    __syncthreads();

    if (t == 0) {               // 128-long serial smem scan per bin: trivial
        int run = 0;
        for (int k = 0; k < TPB_BIN; k++) {
            int c = s_part[b][k];
            s_part[b][k] = run;
            run += c;
        }
        g_totals[b] = run;
    }
    __syncthreads();

    int run = s_part[b][t];
    for (int blk = lo; blk < hi; blk++) {
        int c = g_blockCounts[blk * NBINS + b];
        g_blockOffsets[blk * NBINS + b] = run;
        run += c;
    }
}

// ---------------------------------------------------------------------------
// Pass 3: stable rank within block (packed 8x16-bit block scan) + scatter copy.
// Copy phase: 16 threads per point, one float4 each -> 256B coalesced per point.
// ---------------------------------------------------------------------------
__global__ __launch_bounds__(THREADS)
void scatter_kernel(const int* __restrict__ inds,
                    const float4* __restrict__ feat,
                    float4* __restrict__ out,
                    int n, int max_length) {
    __shared__ uint8_t  s_b[PPB];
    __shared__ int      s_dst[PPB];
    __shared__ uint32_t s_scan[THREADS][4];
    __shared__ int      s_off[NBINS];

    int tid  = threadIdx.x;
    int base = blockIdx.x * PPB;
    int cnt  = min(PPB, n - base);

    // coalesced load of b values into smem
    for (int j = tid; j < cnt; j += THREADS)
        s_b[j] = (uint8_t)(inds[(size_t)(base + j) * 4] & (NBINS - 1));
    if (tid < NBINS)
        s_off[tid] = g_blockOffsets[blockIdx.x * NBINS + tid];
    __syncthreads();

    // per-thread counts over its contiguous ITEMS, packed 2x16-bit per word
    uint32_t c[4] = {0, 0, 0, 0};
    int lo = tid * ITEMS;
#pragma unroll
    for (int k = 0; k < ITEMS; k++) {
        int j = lo + k;
        if (j < cnt) {
            int b = s_b[j];
            c[b >> 1] += (1u << ((b & 1) * 16));
        }
    }

    // Hillis-Steele inclusive scan over threads (vector of 4 packed words)
    uint32_t x[4];
#pragma unroll
    for (int i = 0; i < 4; i++) { x[i] = c[i]; s_scan[tid][i] = x[i]; }
    for (int off = 1; off < THREADS; off <<= 1) {
        __syncthreads();
        uint32_t t4[4] = {0, 0, 0, 0};
        if (tid >= off) {
#pragma unroll
            for (int i = 0; i < 4; i++) t4[i] = s_scan[tid - off][i];
        }
        __syncthreads();
#pragma unroll
        for (int i = 0; i < 4; i++) { x[i] += t4[i]; s_scan[tid][i] = x[i]; }
    }
    // exclusive prefix for this thread
    uint32_t p[4];
#pragma unroll
    for (int i = 0; i < 4; i++) p[i] = x[i] - c[i];
    __syncthreads();

    // replay: assign stable ranks, compute destination row indices
#pragma unroll
    for (int k = 0; k < ITEMS; k++) {
        int j = lo + k;
        if (j < cnt) {
            int b   = s_b[j];
            int sh  = (b & 1) * 16;
            int w   = b >> 1;
            int pos = s_off[b] + (int)((p[w] >> sh) & 0xFFFFu);
            p[w] += (1u << sh);
            s_dst[j] = (pos < max_length) ? (b * max_length + pos) : -1;
        }
    }
    __syncthreads();

    // cooperative copy: group of 16 threads per point, float4 lanes
    int group = tid >> 4;   // 0..15
    int lane  = tid & 15;   // 0..15 float4 slots (64 floats)
#pragma unroll 4
    for (int j = group; j < cnt; j += 16) {
        int d = s_dst[j];
        float4 v = feat[(size_t)(base + j) * 16 + lane];
        if (d >= 0)
            out[(size_t)d * 16 + lane] = v;
    }
}

// ---------------------------------------------------------------------------
// Pass 4: zero only the unwritten tails out[b, counts[b]:max_length, :]
// ---------------------------------------------------------------------------
__global__ __launch_bounds__(THREADS)
void zero_tail_kernel(float4* __restrict__ out, int max_length) {
    int b = blockIdx.y;
    int c = min(g_totals[b], max_length);
    size_t start  = ((size_t)b * max_length + c) * 16;
    size_t end    = ((size_t)(b + 1) * max_length) * 16;
    size_t stride = (size_t)gridDim.x * blockDim.x;
    float4 z = make_float4(0.f, 0.f, 0.f, 0.f);
    for (size_t i = start + (size_t)blockIdx.x * blockDim.x + threadIdx.x;
         i < end; i += stride)
        out[i] = z;
}

// ---------------------------------------------------------------------------
extern "C" void kernel_launch(void* const* d_in, const int* in_sizes, int n_in,
                              void* d_out, int out_size) {
    const int*    inds = (const int*)d_in[0];
    const float4* feat = (const float4*)d_in[1];
    float4*       out  = (float4*)d_out;

    int n = in_sizes[0] / 4;                  // points (inds is [N,4])
    int C = in_sizes[1] / n;                  // 64
    const int bs = NBINS;                     // fixed at 8 for this problem
    int max_length = out_size / (bs * C);     // 256000

    int nblocks = (n + PPB - 1) / PPB;
    if (nblocks > MAX_BLOCKS) nblocks = MAX_BLOCKS;  // (n fits: 977 blocks)

    count_kernel<<<nblocks, THREADS>>>(inds, n);
    scan_kernel<<<1, 1024>>>(nblocks);
    scatter_kernel<<<nblocks, THREADS>>>(inds, feat, out, n, max_length);
    dim3 zgrid(64, NBINS, 1);
    zero_tail_kernel<<<zgrid, THREADS>>>(out, max_length);
}

// round 2
// speedup vs baseline: 1.0115x; 1.0115x over previous
#include <cuda_runtime.h>
#include <stdint.h>

// Fixed-shape bench: N=2e6 points, C=64 floats, bs=8, max_length=out/(8*64).
#define NBINS      8
#define THREADS    256
#define PPB        2048                 // points per block
#define ITEMS      (PPB / THREADS)      // 8 contiguous points per thread
#define MAX_BLOCKS 8192
#define ZBLOCKS    64                   // tail-zero blocks appended to scatter grid

// Scratch (no allocations allowed) — recomputed deterministically every call.
__device__ int g_blockCounts[MAX_BLOCKS * NBINS];
__device__ int g_blockOffsets[MAX_BLOCKS * NBINS];
__device__ int g_totals[NBINS];

// ---------------------------------------------------------------------------
// Pass 1: per-block 8-bin histogram of inds[:,0] (packed per-thread counts,
// warp-reduced, then 32 smem atomics per block).
// ---------------------------------------------------------------------------
__global__ __launch_bounds__(THREADS)
void count_kernel(const int4* __restrict__ inds4, int n) {
    __shared__ int s_cnt[NBINS];
    int tid = threadIdx.x;
    if (tid < NBINS) s_cnt[tid] = 0;
    __syncthreads();

    int base = blockIdx.x * PPB;
    int cnt  = min(PPB, n - base);

    // per-thread packed counts (2 bins per 32-bit word, 16-bit fields)
    uint32_t c[4] = {0, 0, 0, 0};
    int lo = tid * ITEMS;
#pragma unroll
    for (int k = 0; k < ITEMS; k++) {
        int j = lo + k;
        if (j < cnt) {
            int b = inds4[base + j].x & (NBINS - 1);
            c[b >> 1] += (1u << ((b & 1) * 16));
        }
    }
    // warp reduce each packed word
#pragma unroll
    for (int i = 0; i < 4; i++) {
#pragma unroll
        for (int off = 16; off > 0; off >>= 1)
            c[i] += __shfl_down_sync(0xFFFFFFFFu, c[i], off);
    }
    if ((tid & 31) == 0) {
#pragma unroll
        for (int i = 0; i < 4; i++) {
            atomicAdd(&s_cnt[2 * i],     (int)(c[i] & 0xFFFFu));
            atomicAdd(&s_cnt[2 * i + 1], (int)(c[i] >> 16));
        }
    }
    __syncthreads();
    if (tid < NBINS) g_blockCounts[blockIdx.x * NBINS + tid] = s_cnt[tid];
}

// ---------------------------------------------------------------------------
// Pass 2: exclusive scan of block counts per bin (single block, 1024 threads,
// 128 threads per bin so the cross-block chain stays parallel).
// ---------------------------------------------------------------------------
__global__ __launch_bounds__(1024)
void scan_kernel(int nblocks) {
    const int TPB_BIN = 128;
    int b = threadIdx.x / TPB_BIN;
    int t = threadIdx.x % TPB_BIN;
    int per = (nblocks + TPB_BIN - 1) / TPB_BIN;
    int lo = t * per;
    int hi = min(lo + per, nblocks);

    int sum = 0;
    for (int blk = lo; blk < hi; blk++)
        sum += g_blockCounts[blk * NBINS + b];

    __shared__ int s_part[NBINS][TPB_BIN];
    s_part[b][t] = sum;
    __syncthreads();

    if (t == 0) {
        int run = 0;
        for (int k = 0; k < TPB_BIN; k++) {
            int c = s_part[b][k];
            s_part[b][k] = run;
            run += c;
        }
        g_totals[b] = run;
    }
    __syncthreads();

    int run = s_part[b][t];
    for (int blk = lo; blk < hi; blk++) {
        int c = g_blockCounts[blk * NBINS + b];
        g_blockOffsets[blk * NBINS + b] = run;
        run += c;
    }
}

// ---------------------------------------------------------------------------
// Pass 3 (fused): blocks [0, nblocks) do stable-rank + scatter copy;
// blocks [nblocks, nblocks+ZBLOCKS) zero the unwritten output tails
// (g_totals is ready — scan ran before this kernel). Tail zeroing overlaps
// the 1 GB streaming pass instead of serializing after it.
// ---------------------------------------------------------------------------
__global__ __launch_bounds__(THREADS)
void scatter_fused_kernel(const int4* __restrict__ inds4,
                          const float4* __restrict__ feat,
                          float4* __restrict__ out,
                          int n, int max_length, int nblocks) {
    // ---- tail-zero blocks --------------------------------------------------
    if ((int)blockIdx.x >= nblocks) {
        int z   = blockIdx.x - nblocks;          // 0..63
        int bin = z >> 3;                        // 8 blocks per bin
        int sub = z & 7;
        int c   = min(g_totals[bin], max_length);
        size_t start  = ((size_t)bin * max_length + c) * 16;
        size_t end    = ((size_t)(bin + 1) * max_length) * 16;
        size_t stride = (size_t)8 * THREADS;
        float4 zf = make_float4(0.f, 0.f, 0.f, 0.f);
        for (size_t i = start + (size_t)sub * THREADS + threadIdx.x;
             i < end; i += stride)
            out[i] = zf;
        return;
    }

    // ---- scatter blocks ----------------------------------------------------
    __shared__ uint8_t  s_b[PPB];
    __shared__ int      s_dst[PPB];
    __shared__ uint32_t s_wtot[THREADS / 32][4];   // warp-inclusive totals
    __shared__ uint32_t s_wexc[THREADS / 32][4];   // warp exclusive offsets
    __shared__ int      s_off[NBINS];

    int tid  = threadIdx.x;
    int wid  = tid >> 5;
    int lane = tid & 31;
    int base = blockIdx.x * PPB;
    int cnt  = min(PPB, n - base);

    // coalesced load of b values into smem (one int4 per point)
    for (int j = tid; j < cnt; j += THREADS)
        s_b[j] = (uint8_t)(inds4[base + j].x & (NBINS - 1));
    if (tid < NBINS)
        s_off[tid] = g_blockOffsets[blockIdx.x * NBINS + tid];
    __syncthreads();

    // per-thread packed counts over contiguous ITEMS (2 bins / word, 16-bit)
    uint32_t c[4] = {0, 0, 0, 0};
    int lo = tid * ITEMS;
#pragma unroll
    for (int k = 0; k < ITEMS; k++) {
        int j = lo + k;
        if (j < cnt) {
            int b = s_b[j];
            c[b >> 1] += (1u << ((b & 1) * 16));
        }
    }

    // warp-level inclusive scan of the packed vector (no barriers)
    uint32_t inc[4];
#pragma unroll
    for (int i = 0; i < 4; i++) inc[i] = c[i];
#pragma unroll
    for (int off = 1; off < 32; off <<= 1) {
#pragma unroll
        for (int i = 0; i < 4; i++) {
            uint32_t v = __shfl_up_sync(0xFFFFFFFFu, inc[i], off);
            if (lane >= off) inc[i] += v;
        }
    }
    if (lane == 31) {
#pragma unroll
        for (int i = 0; i < 4; i++) s_wtot[wid][i] = inc[i];
    }
    __syncthreads();

    // warp 0 scans the 8 warp totals (4 words × 8 warps = 32 lanes)
    if (wid == 0) {
        int word = lane >> 3;   // 0..3
        int w    = lane & 7;    // warp index 0..7
        uint32_t orig = s_wtot[w][word];
        uint32_t v = orig;
#pragma unroll
        for (int off = 1; off < 8; off <<= 1) {
            uint32_t t = __shfl_up_sync(0xFFFFFFFFu, v, off);
            if ((lane & 7) >= off) v += t;
        }
        s_wexc[w][word] = v - orig;   // exclusive across warps
    }
    __syncthreads();

    // exclusive prefix for this thread
    uint32_t p[4];
#pragma unroll
    for (int i = 0; i < 4; i++) p[i] = inc[i] - c[i] + s_wexc[wid][i];

    // replay: assign stable ranks, compute destination row indices
#pragma unroll
    for (int k = 0; k < ITEMS; k++) {
        int j = lo + k;
        if (j < cnt) {
            int b   = s_b[j];
            int sh  = (b & 1) * 16;
            int w   = b >> 1;
            int pos = s_off[b] + (int)((p[w] >> sh) & 0xFFFFu);
            p[w] += (1u << sh);
            s_dst[j] = (pos < max_length) ? (b * max_length + pos) : -1;
        }
    }
    __syncthreads();

    // cooperative copy: 16 threads per point, one float4 lane each (256B rows)
    int group = tid >> 4;   // 0..15
    int flane = tid & 15;   // float4 slot 0..15
#pragma unroll 4
    for (int j = group; j < cnt; j += 16) {
        int d = s_dst[j];
        float4 v = feat[(size_t)(base + j) * 16 + flane];
        if (d >= 0)
            out[(size_t)d * 16 + flane] = v;
    }
}

// ---------------------------------------------------------------------------
extern "C" void kernel_launch(void* const* d_in, const int* in_sizes, int n_in,
                              void* d_out, int out_size) {
    const int4*   inds4 = (const int4*)d_in[0];
    const float4* feat  = (const float4*)d_in[1];
    float4*       out   = (float4*)d_out;

    int n = in_sizes[0] / 4;                  // points (inds is [N,4])
    int C = in_sizes[1] / n;                  // 64
    int max_length = out_size / (NBINS * C);  // 256000

    int nblocks = (n + PPB - 1) / PPB;
    if (nblocks > MAX_BLOCKS) nblocks = MAX_BLOCKS;

    count_kernel<<<nblocks, THREADS>>>(inds4, n);
    scan_kernel<<<1, 1024>>>(nblocks);
    scatter_fused_kernel<<<nblocks + ZBLOCKS, THREADS>>>(inds4, feat, out,
                                                         n, max_length, nblocks);
}

// round 3
// speedup vs baseline: 1.0361x; 1.0243x over previous
#include <cuda_runtime.h>
#include <stdint.h>

// Fixed-shape bench: N=2e6 points, C=64 floats, bs=8, max_length=out/(8*64).
#define NBINS      8
#define THREADS    256
#define PPB        2048                 // points per block
#define ITEMS      (PPB / THREADS)      // 8 contiguous points per thread
#define MAX_BLOCKS 8192
#define ZBLOCKS    64                   // tail-zero tickets appended to grid
#define FULLMASK   0xFFFFFFFFu

// Scratch (no allocs allowed). Reset each call by init_kernel -> deterministic.
__device__ int g_ticket;
__device__ int g_flag[MAX_BLOCKS];              // 0=none, 1=agg ready, 2=incl ready
__device__ int g_agg [MAX_BLOCKS * NBINS];
__device__ int g_incl[MAX_BLOCKS * NBINS];
__device__ int g_totFlag;
__device__ int g_totals[NBINS];

// ---------------------------------------------------------------------------
// Reset lookback state (tiny; required for graph-replay determinism).
// ---------------------------------------------------------------------------
__global__ void init_kernel(int nblocks) {
    int i = blockIdx.x * blockDim.x + threadIdx.x;
    if (i == 0) { g_ticket = 0; g_totFlag = 0; }
    for (int j = i; j < nblocks; j += gridDim.x * blockDim.x)
        g_flag[j] = 0;
}

// ---------------------------------------------------------------------------
// Single fused pass: histogram + decoupled-lookback prefix + stable scatter,
// with tail-zero work appended as extra tickets.
// ---------------------------------------------------------------------------
__global__ __launch_bounds__(THREADS)
void fused_kernel(const int4* __restrict__ inds4,
                  const float4* __restrict__ feat,
                  float4* __restrict__ out,
                  int n, int max_length, int nblocks) {
    __shared__ int      s_vbid;
    __shared__ uint8_t  s_b[PPB];
    __shared__ int      s_dst[PPB];
    __shared__ uint32_t s_wtot[THREADS / 32][4];   // warp-inclusive totals
    __shared__ uint32_t s_wexc[THREADS / 32][4];   // warp exclusive offsets
    __shared__ int      s_off[NBINS];              // this block's per-bin base

    int tid  = threadIdx.x;
    int wid  = tid >> 5;
    int lane = tid & 31;

    if (tid == 0) s_vbid = atomicAdd(&g_ticket, 1);
    __syncthreads();
    int vbid = s_vbid;

    // ---- tail-zero tickets -------------------------------------------------
    if (vbid >= nblocks) {
        if (tid == 0) {
            while (*(volatile int*)&g_totFlag == 0) { }
        }
        __syncthreads();
        __threadfence();
        int z   = vbid - nblocks;            // 0..ZBLOCKS-1
        int bin = z >> 3;                    // 8 tickets per bin
        int sub = z & 7;
        int c   = min(g_totals[bin], max_length);
        size_t start  = ((size_t)bin * max_length + c) * 16;
        size_t end    = ((size_t)(bin + 1) * max_length) * 16;
        size_t stride = (size_t)8 * THREADS;
        float4 zf = make_float4(0.f, 0.f, 0.f, 0.f);
        for (size_t i = start + (size_t)sub * THREADS + tid; i < end; i += stride)
            out[i] = zf;
        return;
    }

    // ---- scatter tickets ---------------------------------------------------
    int base = vbid * PPB;
    int cnt  = min(PPB, n - base);

    // coalesced load of b values into smem (one int4 per point; only read of inds)
    for (int j = tid; j < cnt; j += THREADS)
        s_b[j] = (uint8_t)(inds4[base + j].x & (NBINS - 1));
    __syncthreads();

    // per-thread packed counts over contiguous ITEMS (2 bins / word, 16-bit)
    uint32_t c[4] = {0, 0, 0, 0};
    int lo = tid * ITEMS;
#pragma unroll
    for (int k = 0; k < ITEMS; k++) {
        int j = lo + k;
        if (j < cnt) {
            int b = s_b[j];
            c[b >> 1] += (1u << ((b & 1) * 16));
        }
    }

    // warp-level inclusive scan of the packed vector
    uint32_t inc[4];
#pragma unroll
    for (int i = 0; i < 4; i++) inc[i] = c[i];
#pragma unroll
    for (int off = 1; off < 32; off <<= 1) {
#pragma unroll
        for (int i = 0; i < 4; i++) {
            uint32_t v = __shfl_up_sync(FULLMASK, inc[i], off);
            if (lane >= off) inc[i] += v;
        }
    }
    if (lane == 31) {
#pragma unroll
        for (int i = 0; i < 4; i++) s_wtot[wid][i] = inc[i];
    }
    __syncthreads();

    // ---- warp 0: publish aggregate, inter-warp scan, decoupled lookback ----
    if (wid == 0) {
        // block aggregate per bin (lanes 0..7)
        int agg = 0;
        if (lane < NBINS) {
            int w4 = lane >> 1, sh = (lane & 1) * 16;
#pragma unroll
            for (int w = 0; w < THREADS / 32; w++)
                agg += (int)((s_wtot[w][w4] >> sh) & 0xFFFFu);
        }
        if (vbid > 0) {
            if (lane < NBINS) g_agg[vbid * NBINS + lane] = agg;
            __threadfence();
            if (lane == 0) *(volatile int*)&g_flag[vbid] = 1;
        }

        // inter-warp exclusive scan of warp totals (32 lanes: 4 words x 8 warps)
        {
            int word = lane >> 3;
            int w    = lane & 7;
            uint32_t orig = s_wtot[w][word];
            uint32_t v = orig;
#pragma unroll
            for (int off = 1; off < 8; off <<= 1) {
                uint32_t t = __shfl_up_sync(FULLMASK, v, off);
                if ((lane & 7) >= off) v += t;
            }
            s_wexc[w][word] = v - orig;
        }

        // decoupled lookback: 4 predecessors per iteration
        int run = 0;
        int pred = vbid - 1;
        while (pred >= 0) {
            int npred = min(4, pred + 1);
            int f = 0;
            if (lane < npred) {
                do { f = *(volatile int*)&g_flag[pred - lane]; } while (f == 0);
            }
            unsigned m2 = __ballot_sync(FULLMASK, (lane < npred) && (f == 2));
            int d2 = m2 ? (__ffs(m2) - 1) : npred;   // nearest prefix-ready
            __threadfence();
            if (lane < NBINS) {
                for (int d = 0; d < d2; d++)
                    run += g_agg[(pred - d) * NBINS + lane];
                if (d2 < npred)
                    run += g_incl[(pred - d2) * NBINS + lane];
            }
            if (d2 < npred) break;
            pred -= npred;
        }

        if (lane < NBINS) {
            s_off[lane] = run;
            g_incl[vbid * NBINS + lane] = run + agg;
            if (vbid == nblocks - 1) g_totals[lane] = run + agg;
        }
        __threadfence();
        if (lane == 0) {
            *(volatile int*)&g_flag[vbid] = 2;
            if (vbid == nblocks - 1) *(volatile int*)&g_totFlag = 1;
        }
    }
    __syncthreads();

    // exclusive prefix for this thread
    uint32_t p[4];
#pragma unroll
    for (int i = 0; i < 4; i++) p[i] = inc[i] - c[i] + s_wexc[wid][i];

    // replay: assign stable ranks, compute destination rows
#pragma unroll
    for (int k = 0; k < ITEMS; k++) {
        int j = lo + k;
        if (j < cnt) {
            int b   = s_b[j];
            int sh  = (b & 1) * 16;
            int w   = b >> 1;
            int pos = s_off[b] + (int)((p[w] >> sh) & 0xFFFFu);
            p[w] += (1u << sh);
            s_dst[j] = (pos < max_length) ? (b * max_length + pos) : -1;
        }
    }
    __syncthreads();

    // cooperative copy: 16 threads per point, one float4 lane each (256B rows)
    int group = tid >> 4;
    int flane = tid & 15;
#pragma unroll 4
    for (int j = group; j < cnt; j += 16) {
        int d = s_dst[j];
        float4 v = feat[(size_t)(base + j) * 16 + flane];
        if (d >= 0)
            out[(size_t)d * 16 + flane] = v;
    }
}

// ---------------------------------------------------------------------------
extern "C" void kernel_launch(void* const* d_in, const int* in_sizes, int n_in,
                              void* d_out, int out_size) {
    const int4*   inds4 = (const int4*)d_in[0];
    const float4* feat  = (const float4*)d_in[1];
    float4*       out   = (float4*)d_out;

    int n = in_sizes[0] / 4;                  // points (inds is [N,4])
    int C = in_sizes[1] / n;                  // 64
    int max_length = out_size / (NBINS * C);  // 256000

    int nblocks = (n + PPB - 1) / PPB;
    if (nblocks > MAX_BLOCKS) nblocks = MAX_BLOCKS;

    init_kernel<<<2, 1024>>>(nblocks);
    fused_kernel<<<nblocks + ZBLOCKS, THREADS>>>(inds4, feat, out,
                                                 n, max_length, nblocks);
}